// round 2
// baseline (speedup 1.0000x reference)
#include <cuda_runtime.h>
#include <cuda_bf16.h>
#include <math.h>

#define B 64
#define S 4096
#define D 1024
#define NSPLIT 8
#define SPS (S / NSPLIT)   // 512
#define TILE 8

// ---------------- scratch (device globals: no allocation allowed) ----------
__device__ float g_q[B * D];                 // 256 KB  q = query @ W_align^T
__device__ float g_scores[B * S];            // 1 MB    masked raw scores
__device__ float g_pm[B * NSPLIT];           // per-split running max
__device__ float g_pl[B * NSPLIT];           // per-split running sum
__device__ float g_pacc[B * NSPLIT * D];     // 2 MB    per-split unnormalized acc
__device__ float g_wc[B * D];                // weight_context
__device__ float g_lin[B * D];               // pre-tanh accumulator

// ---------------- zero init for atomic accumulators ------------------------
__global__ void zero_kernel() {
    int i = blockIdx.x * blockDim.x + threadIdx.x;   // 64*256 = 16384 float4 per array
    float4 z = make_float4(0.f, 0.f, 0.f, 0.f);
    reinterpret_cast<float4*>(g_q)[i] = z;
    reinterpret_cast<float4*>(g_lin)[i] = z;
}

// ---------------- small skinny GEMM: out[b,d] += sum_k A[b,k] * W[d,k] -----
// grid.x = D/32 tiles of d ; grid.y in [0,8): (y&3)=k-split of 256, (y>>2)=operand pair
#define BN 32
#define BK 32
#define KCHUNK 256

__global__ void __launch_bounds__(256) gemm_nt(
    const float* __restrict__ A0, const float* __restrict__ W0,
    const float* __restrict__ A1, const float* __restrict__ W1,
    float* __restrict__ out)
{
    const int which = blockIdx.y >> 2;
    const float* __restrict__ A = which ? A1 : A0;
    const float* __restrict__ W = which ? W1 : W0;
    const int k0  = (blockIdx.y & 3) * KCHUNK;
    const int dn0 = blockIdx.x * BN;

    __shared__ float As[64][BK + 1];
    __shared__ float Ws[BN][BK + 1];

    const int tid = threadIdx.x;
    const int tx = tid & 15;   // d pair
    const int ty = tid >> 4;   // b quad
    float acc[4][2] = {};

    for (int bk = 0; bk < KCHUNK; bk += BK) {
        // load A tile: 64 rows x 32 k = 512 float4 (2 per thread)
        #pragma unroll
        for (int r = 0; r < 2; r++) {
            int idx = tid + r * 256;
            int bb = idx >> 3, kk4 = idx & 7;
            float4 v = *reinterpret_cast<const float4*>(A + bb * D + k0 + bk + kk4 * 4);
            As[bb][kk4 * 4 + 0] = v.x; As[bb][kk4 * 4 + 1] = v.y;
            As[bb][kk4 * 4 + 2] = v.z; As[bb][kk4 * 4 + 3] = v.w;
        }
        // load W tile: 32 rows x 32 k = 256 float4 (1 per thread)
        {
            int dd = tid >> 3, kk4 = tid & 7;
            float4 v = *reinterpret_cast<const float4*>(W + (size_t)(dn0 + dd) * D + k0 + bk + kk4 * 4);
            Ws[dd][kk4 * 4 + 0] = v.x; Ws[dd][kk4 * 4 + 1] = v.y;
            Ws[dd][kk4 * 4 + 2] = v.z; Ws[dd][kk4 * 4 + 3] = v.w;
        }
        __syncthreads();
        #pragma unroll
        for (int kk = 0; kk < BK; kk++) {
            float w0 = Ws[tx * 2][kk];
            float w1 = Ws[tx * 2 + 1][kk];
            #pragma unroll
            for (int i = 0; i < 4; i++) {
                float a = As[ty * 4 + i][kk];
                acc[i][0] = fmaf(a, w0, acc[i][0]);
                acc[i][1] = fmaf(a, w1, acc[i][1]);
            }
        }
        __syncthreads();
    }
    #pragma unroll
    for (int i = 0; i < 4; i++) {
        int b = ty * 4 + i;
        atomicAdd(&out[b * D + dn0 + tx * 2 + 0], acc[i][0]);
        atomicAdd(&out[b * D + dn0 + tx * 2 + 1], acc[i][1]);
    }
}

// ---------------- flash pass over context (the 1 GiB read) -----------------
// grid = (NSPLIT, B), 256 threads. Thread t owns output columns [4t, 4t+4).
// Each tile: 8 rows held fully in registers (8 x float4/thread); dot-products
// reduced warp-wise then across 8 warps via shared; online softmax; register
// accumulate. Context touched exactly once from HBM, never staged in smem.
__global__ void __launch_bounds__(256, 4) attn_flash(
    const float* __restrict__ ctx, const int* __restrict__ mask)
{
    const int split = blockIdx.x;
    const int b     = blockIdx.y;
    const int tid   = threadIdx.x;
    const int lane  = tid & 31;
    const int wid   = tid >> 5;

    __shared__ float sh_red[64];      // [j*8 + warp]
    __shared__ float sh_align[TILE];

    // q slice for my 4 columns, held in registers for the whole kernel
    const float4 qr = *reinterpret_cast<const float4*>(g_q + b * D + tid * 4);

    float acc0 = 0.f, acc1 = 0.f, acc2 = 0.f, acc3 = 0.f;
    float m_run = -1e30f, l_run = 0.f;

    const float* __restrict__ cbase = ctx + (size_t)b * S * D + (size_t)split * SPS * D + tid * 4;
    const int*   __restrict__ mbase = mask + b * S + split * SPS;
    const int    sgbase = b * S + split * SPS;

    for (int s0 = 0; s0 < SPS; s0 += TILE) {
        const float* tb = cbase + (size_t)s0 * D;
        float4 f[TILE];
        #pragma unroll
        for (int j = 0; j < TILE; j++)
            f[j] = *reinterpret_cast<const float4*>(tb + (size_t)j * D);

        // per-thread partial dots for the 8 rows
        float p[TILE];
        #pragma unroll
        for (int j = 0; j < TILE; j++)
            p[j] = fmaf(f[j].x, qr.x, fmaf(f[j].y, qr.y, fmaf(f[j].z, qr.z, f[j].w * qr.w)));

        // warp reduce each row-partial
        #pragma unroll
        for (int j = 0; j < TILE; j++) {
            #pragma unroll
            for (int off = 16; off > 0; off >>= 1)
                p[j] += __shfl_down_sync(0xffffffffu, p[j], off);
        }
        if (lane == 0) {
            #pragma unroll
            for (int j = 0; j < TILE; j++) sh_red[j * 8 + wid] = p[j];
        }
        __syncthreads();

        // cross-warp reduce (threads 0..63, groups of 8) + mask + score store
        if (tid < 64) {
            float v = sh_red[tid];
            v += __shfl_down_sync(0xffffffffu, v, 4, 8);
            v += __shfl_down_sync(0xffffffffu, v, 2, 8);
            v += __shfl_down_sync(0xffffffffu, v, 1, 8);
            if ((tid & 7) == 0) {
                int j = tid >> 3;
                float a = (mbase[s0 + j] != 0) ? v : -1e30f;
                g_scores[sgbase + s0 + j] = a;
                sh_align[j] = a;
            }
        }
        __syncthreads();

        // online softmax update (replicated per thread)
        float new_m = m_run;
        #pragma unroll
        for (int j = 0; j < TILE; j++) new_m = fmaxf(new_m, sh_align[j]);
        float scale = __expf(m_run - new_m);
        float w[TILE];
        float wsum = 0.f;
        #pragma unroll
        for (int j = 0; j < TILE; j++) {
            float a = sh_align[j];
            w[j] = (a > -1e29f) ? __expf(a - new_m) : 0.f;
            wsum += w[j];
        }
        m_run = new_m;
        l_run = fmaf(l_run, scale, wsum);
        acc0 *= scale; acc1 *= scale; acc2 *= scale; acc3 *= scale;
        #pragma unroll
        for (int j = 0; j < TILE; j++) {
            acc0 = fmaf(w[j], f[j].x, acc0);
            acc1 = fmaf(w[j], f[j].y, acc1);
            acc2 = fmaf(w[j], f[j].z, acc2);
            acc3 = fmaf(w[j], f[j].w, acc3);
        }
        // no extra sync needed: next writes to sh_align are gated by the two
        // barriers above; sh_red producers can't pass the second barrier early.
    }

    // write split partials
    if (tid == 0) {
        g_pm[b * NSPLIT + split] = m_run;
        g_pl[b * NSPLIT + split] = l_run;
    }
    float* pa = g_pacc + (size_t)(b * NSPLIT + split) * D + tid * 4;
    pa[0] = acc0; pa[1] = acc1; pa[2] = acc2; pa[3] = acc3;
}

// ---------------- combine splits, normalize attention, emit weight_context -
__global__ void __launch_bounds__(256) combine_kernel(float* __restrict__ out_att,
                                                      float* __restrict__ out_wc)
{
    const int b = blockIdx.x;
    const int tid = threadIdx.x;
    __shared__ float sm[NSPLIT], sl[NSPLIT];
    if (tid < NSPLIT) {
        sm[tid] = g_pm[b * NSPLIT + tid];
        sl[tid] = g_pl[b * NSPLIT + tid];
    }
    __syncthreads();

    float M = -1e30f;
    #pragma unroll
    for (int i = 0; i < NSPLIT; i++) M = fmaxf(M, sm[i]);
    float fac[NSPLIT];
    float L = 0.f;
    #pragma unroll
    for (int i = 0; i < NSPLIT; i++) {
        fac[i] = __expf(sm[i] - M);
        L = fmaf(sl[i], fac[i], L);
    }
    const float invL = 1.f / L;

    #pragma unroll
    for (int jj = 0; jj < 4; jj++) {
        int d = tid + 256 * jj;
        float acc = 0.f;
        #pragma unroll
        for (int i = 0; i < NSPLIT; i++)
            acc = fmaf(fac[i], g_pacc[(size_t)(b * NSPLIT + i) * D + d], acc);
        float wc = acc * invL;
        g_wc[b * D + d] = wc;
        out_wc[b * D + d] = wc;
    }

    for (int s = tid; s < S; s += 256)
        out_att[b * S + s] = __expf(g_scores[b * S + s] - M) * invL;
}

// ---------------- tanh epilogue --------------------------------------------
__global__ void tanh_kernel(float* __restrict__ out) {
    int i = (blockIdx.x * blockDim.x + threadIdx.x) * 4;
    float4 v = *reinterpret_cast<const float4*>(g_lin + i);
    float4 r = make_float4(tanhf(v.x), tanhf(v.y), tanhf(v.z), tanhf(v.w));
    *reinterpret_cast<float4*>(out + i) = r;
}

// ---------------- launcher --------------------------------------------------
extern "C" void kernel_launch(void* const* d_in, const int* in_sizes, int n_in,
                              void* d_out, int out_size)
{
    const float* query     = (const float*)d_in[0];   // [B, D]
    const float* context   = (const float*)d_in[1];   // [B, S, D]
    const int*   ctx_mask  = (const int*)  d_in[2];   // [B, S]
    const float* W_align   = (const float*)d_in[3];   // [D, D]
    const float* W_context = (const float*)d_in[4];   // [D, D]
    const float* W_query   = (const float*)d_in[5];   // [D, D]

    float* out  = (float*)d_out;                      // [B, D]      65536
    float* att  = out + B * D;                        // [B, S]      262144
    float* owc  = att + B * S;                        // [B, D]      65536

    // Host-visible addresses of ALL device symbols passed as kernel args.
    // (Round-1 bug: passing g_wc directly from host code hands the kernel the
    //  host shadow address — garbage on device.)
    float *pq = nullptr, *plin = nullptr, *pwc = nullptr;
    cudaGetSymbolAddress((void**)&pq,   g_q);
    cudaGetSymbolAddress((void**)&plin, g_lin);
    cudaGetSymbolAddress((void**)&pwc,  g_wc);

    // 1. zero atomic accumulators
    zero_kernel<<<64, 256>>>();

    // 2. q = query @ W_align^T   (split-K x4)
    gemm_nt<<<dim3(D / BN, 4), 256>>>(query, W_align, query, W_align, pq);

    // 3. flash pass over context (1 GiB, read once)
    attn_flash<<<dim3(NSPLIT, B), 256>>>(context, ctx_mask);

    // 4. combine splits -> attention + weight_context
    combine_kernel<<<B, 256>>>(att, owc);

    // 5. g_lin = wc @ W_context^T + query @ W_query^T  (8 blocks.y: 2 operands x 4 k-splits)
    gemm_nt<<<dim3(D / BN, 8), 256>>>(pwc, W_context, query, W_query, plin);

    // 6. out = tanh(g_lin)
    tanh_kernel<<<64, 256>>>(out);
}

// round 3
// speedup vs baseline: 1.2450x; 1.2450x over previous
#include <cuda_runtime.h>
#include <cuda_bf16.h>
#include <math.h>

#define B 64
#define S 4096
#define D 1024
#define NSPLIT 8
#define SPS (S / NSPLIT)   // 512
#define TILE 8
#define NTILE (SPS / TILE) // 64

// ---------------- scratch (device globals: no allocation allowed) ----------
__device__ float g_q[B * D];                 // 256 KB  q = query @ W_align^T
__device__ float g_scores[B * S];            // 1 MB    masked raw scores
__device__ float g_pm[B * NSPLIT];           // per-split running max
__device__ float g_pl[B * NSPLIT];           // per-split running sum
__device__ float g_pacc[B * NSPLIT * D];     // 2 MB    per-split unnormalized acc
__device__ float g_wc[B * D];                // weight_context
__device__ float g_lin[B * D];               // pre-tanh accumulator

// ---------------- zero init for atomic accumulators ------------------------
__global__ void zero_kernel() {
    int i = blockIdx.x * blockDim.x + threadIdx.x;   // 64*256 = 16384 float4 per array
    float4 z = make_float4(0.f, 0.f, 0.f, 0.f);
    reinterpret_cast<float4*>(g_q)[i] = z;
    reinterpret_cast<float4*>(g_lin)[i] = z;
}

// ---------------- small skinny GEMM: out[b,d] += sum_k A[b,k] * W[d,k] -----
// grid.x = D/32 d-tiles; grid.y = 2*KS: (y>>3)=operand pair, (y&7)=k-split of 128
#define BN 32
#define BK 32
#define KS 8
#define KCHUNK (D / KS)    // 128

__global__ void __launch_bounds__(256) gemm_nt(
    const float* __restrict__ A0, const float* __restrict__ W0,
    const float* __restrict__ A1, const float* __restrict__ W1,
    float* __restrict__ out)
{
    const int which = blockIdx.y >> 3;
    const float* __restrict__ A = which ? A1 : A0;
    const float* __restrict__ W = which ? W1 : W0;
    const int k0  = (blockIdx.y & (KS - 1)) * KCHUNK;
    const int dn0 = blockIdx.x * BN;

    __shared__ float As[64][BK + 1];
    __shared__ float Ws[BN][BK + 1];

    const int tid = threadIdx.x;
    const int tx = tid & 15;   // d pair
    const int ty = tid >> 4;   // b quad
    float acc[4][2] = {};

    for (int bk = 0; bk < KCHUNK; bk += BK) {
        #pragma unroll
        for (int r = 0; r < 2; r++) {
            int idx = tid + r * 256;
            int bb = idx >> 3, kk4 = idx & 7;
            float4 v = *reinterpret_cast<const float4*>(A + bb * D + k0 + bk + kk4 * 4);
            As[bb][kk4 * 4 + 0] = v.x; As[bb][kk4 * 4 + 1] = v.y;
            As[bb][kk4 * 4 + 2] = v.z; As[bb][kk4 * 4 + 3] = v.w;
        }
        {
            int dd = tid >> 3, kk4 = tid & 7;
            float4 v = *reinterpret_cast<const float4*>(W + (size_t)(dn0 + dd) * D + k0 + bk + kk4 * 4);
            Ws[dd][kk4 * 4 + 0] = v.x; Ws[dd][kk4 * 4 + 1] = v.y;
            Ws[dd][kk4 * 4 + 2] = v.z; Ws[dd][kk4 * 4 + 3] = v.w;
        }
        __syncthreads();
        #pragma unroll
        for (int kk = 0; kk < BK; kk++) {
            float w0 = Ws[tx * 2][kk];
            float w1 = Ws[tx * 2 + 1][kk];
            #pragma unroll
            for (int i = 0; i < 4; i++) {
                float a = As[ty * 4 + i][kk];
                acc[i][0] = fmaf(a, w0, acc[i][0]);
                acc[i][1] = fmaf(a, w1, acc[i][1]);
            }
        }
        __syncthreads();
    }
    #pragma unroll
    for (int i = 0; i < 4; i++) {
        int b = ty * 4 + i;
        atomicAdd(&out[b * D + dn0 + tx * 2 + 0], acc[i][0]);
        atomicAdd(&out[b * D + dn0 + tx * 2 + 1], acc[i][1]);
    }
}

// ---------------- flash pass over context (the 1 GiB read) -----------------
// grid = (NSPLIT, B), 256 threads, occ 4 (single wave: 512 CTAs <= 592 slots).
// Thread t owns output columns [4t, 4t+4). Context tile is TRANSIENT in
// registers: loaded for the dot, discarded, then re-loaded for the weighted
// accumulate (second read hits L1: 32KB/CTA x 4 CTAs = 128KB < 228KB L1).
// Cross-warp score reduction: 9-shfl butterfly fold -> 8 floats/warp to smem
// (double-buffered) -> ONE barrier -> redundant per-warp combine.
__global__ void __launch_bounds__(256, 4) attn_flash(
    const float* __restrict__ ctx, const int* __restrict__ mask)
{
    const int split = blockIdx.x;
    const int b     = blockIdx.y;
    const int tid   = threadIdx.x;
    const int lane  = tid & 31;
    const int wid   = tid >> 5;

    __shared__ float sh_red[2][8][8];    // [parity][row][warp]

    const float4 qr = *reinterpret_cast<const float4*>(g_q + b * D + tid * 4);

    float acc0 = 0.f, acc1 = 0.f, acc2 = 0.f, acc3 = 0.f;
    float m_run = -1e30f, l_run = 0.f;

    const float* __restrict__ cbase = ctx + (size_t)b * S * D + (size_t)split * SPS * D + tid * 4;
    const int*   __restrict__ mbase = mask + b * S + split * SPS;
    const int    sgbase = b * S + split * SPS;

    const bool h16 = (lane & 16) != 0;
    const bool h8  = (lane & 8)  != 0;
    const bool h4  = (lane & 4)  != 0;
    const int  myrow = lane & 7;

    for (int t = 0; t < NTILE; t++) {
        const int s0 = t * TILE;
        const float* tb = cbase + (size_t)s0 * D;
        const int par = t & 1;

        // ---- dot pass: f transient ----
        float p[TILE];
        #pragma unroll
        for (int j = 0; j < TILE; j++) {
            float4 f = *reinterpret_cast<const float4*>(tb + (size_t)j * D);
            p[j] = fmaf(f.x, qr.x, fmaf(f.y, qr.y, fmaf(f.z, qr.z, f.w * qr.w)));
        }

        // ---- butterfly fold: 8 rows x 32 lanes -> row (lane>>2) ----
        #pragma unroll
        for (int j = 0; j < 4; j++) {
            float send = h16 ? p[j] : p[j + 4];
            float recv = __shfl_xor_sync(0xffffffffu, send, 16);
            p[j] = (h16 ? p[j + 4] : p[j]) + recv;
        }
        #pragma unroll
        for (int j = 0; j < 2; j++) {
            float send = h8 ? p[j] : p[j + 2];
            float recv = __shfl_xor_sync(0xffffffffu, send, 8);
            p[j] = (h8 ? p[j + 2] : p[j]) + recv;
        }
        float pr;
        {
            float send = h4 ? p[0] : p[1];
            float recv = __shfl_xor_sync(0xffffffffu, send, 4);
            pr = (h4 ? p[1] : p[0]) + recv;
        }
        pr += __shfl_xor_sync(0xffffffffu, pr, 2);
        pr += __shfl_xor_sync(0xffffffffu, pr, 1);
        if ((lane & 3) == 0) sh_red[par][lane >> 2][wid] = pr;

        __syncthreads();   // single barrier per tile (smem double-buffered)

        // ---- cross-warp combine (redundant per warp) + mask ----
        float v = 0.f;
        #pragma unroll
        for (int w = 0; w < 8; w++) v += sh_red[par][myrow][w];
        float a = (mbase[s0 + myrow] != 0) ? v : -1e30f;
        if (wid == 0 && lane < 8) g_scores[sgbase + s0 + lane] = a;

        float aj[TILE];
        #pragma unroll
        for (int j = 0; j < TILE; j++)
            aj[j] = __shfl_sync(0xffffffffu, a, j, 8);

        // ---- online softmax ----
        float new_m = m_run;
        #pragma unroll
        for (int j = 0; j < TILE; j++) new_m = fmaxf(new_m, aj[j]);
        float scale = __expf(m_run - new_m);
        float wj[TILE];
        float wsum = 0.f;
        #pragma unroll
        for (int j = 0; j < TILE; j++) {
            wj[j] = (aj[j] > -1e29f) ? __expf(aj[j] - new_m) : 0.f;
            wsum += wj[j];
        }
        m_run = new_m;
        l_run = fmaf(l_run, scale, wsum);
        acc0 *= scale; acc1 *= scale; acc2 *= scale; acc3 *= scale;

        // ---- weighted accumulate: re-load tile (L1 hit) ----
        #pragma unroll
        for (int j = 0; j < TILE; j++) {
            float4 f = *reinterpret_cast<const float4*>(tb + (size_t)j * D);
            acc0 = fmaf(wj[j], f.x, acc0);
            acc1 = fmaf(wj[j], f.y, acc1);
            acc2 = fmaf(wj[j], f.z, acc2);
            acc3 = fmaf(wj[j], f.w, acc3);
        }
    }

    if (tid == 0) {
        g_pm[b * NSPLIT + split] = m_run;
        g_pl[b * NSPLIT + split] = l_run;
    }
    float* pa = g_pacc + (size_t)(b * NSPLIT + split) * D + tid * 4;
    pa[0] = acc0; pa[1] = acc1; pa[2] = acc2; pa[3] = acc3;
}

// ---------------- combine splits, normalize attention, emit weight_context -
// grid (B, 8): block (b, c) handles D/8 cols of wc and S/8 of attention.
__global__ void __launch_bounds__(256) combine_kernel(float* __restrict__ out_att,
                                                      float* __restrict__ out_wc)
{
    const int b = blockIdx.x;
    const int c = blockIdx.y;
    const int tid = threadIdx.x;

    float M = -1e30f;
    float sm[NSPLIT], sl[NSPLIT];
    #pragma unroll
    for (int i = 0; i < NSPLIT; i++) {
        sm[i] = g_pm[b * NSPLIT + i];
        sl[i] = g_pl[b * NSPLIT + i];
        M = fmaxf(M, sm[i]);
    }
    float fac[NSPLIT];
    float L = 0.f;
    #pragma unroll
    for (int i = 0; i < NSPLIT; i++) {
        fac[i] = __expf(sm[i] - M);
        L = fmaf(sl[i], fac[i], L);
    }
    const float invL = 1.f / L;

    // weight_context: 128 cols per block
    if (tid < D / 8) {
        int d = c * (D / 8) + tid;
        float acc = 0.f;
        #pragma unroll
        for (int i = 0; i < NSPLIT; i++)
            acc = fmaf(fac[i], g_pacc[(size_t)(b * NSPLIT + i) * D + d], acc);
        float wc = acc * invL;
        g_wc[b * D + d] = wc;
        out_wc[b * D + d] = wc;
    }

    // attention: 512 scores per block
    #pragma unroll
    for (int r = 0; r < 2; r++) {
        int s = c * (S / 8) + r * 256 + tid;
        out_att[b * S + s] = __expf(g_scores[b * S + s] - M) * invL;
    }
}

// ---------------- tanh epilogue --------------------------------------------
__global__ void tanh_kernel(float* __restrict__ out) {
    int i = (blockIdx.x * blockDim.x + threadIdx.x) * 4;
    float4 v = *reinterpret_cast<const float4*>(g_lin + i);
    float4 r = make_float4(tanhf(v.x), tanhf(v.y), tanhf(v.z), tanhf(v.w));
    *reinterpret_cast<float4*>(out + i) = r;
}

// ---------------- launcher --------------------------------------------------
extern "C" void kernel_launch(void* const* d_in, const int* in_sizes, int n_in,
                              void* d_out, int out_size)
{
    const float* query     = (const float*)d_in[0];   // [B, D]
    const float* context   = (const float*)d_in[1];   // [B, S, D]
    const int*   ctx_mask  = (const int*)  d_in[2];   // [B, S]
    const float* W_align   = (const float*)d_in[3];   // [D, D]
    const float* W_context = (const float*)d_in[4];   // [D, D]
    const float* W_query   = (const float*)d_in[5];   // [D, D]

    float* out  = (float*)d_out;                      // [B, D]
    float* att  = out + B * D;                        // [B, S]
    float* owc  = att + B * S;                        // [B, D]

    // Device addresses of symbols passed as kernel arguments.
    float *pq = nullptr, *plin = nullptr, *pwc = nullptr;
    cudaGetSymbolAddress((void**)&pq,   g_q);
    cudaGetSymbolAddress((void**)&plin, g_lin);
    cudaGetSymbolAddress((void**)&pwc,  g_wc);

    // 1. zero atomic accumulators
    zero_kernel<<<64, 256>>>();

    // 2. q = query @ W_align^T   (split-K x8)
    gemm_nt<<<dim3(D / BN, KS), 256>>>(query, W_align, query, W_align, pq);

    // 3. flash pass over context (1 GiB, read once from DRAM)
    attn_flash<<<dim3(NSPLIT, B), 256>>>(context, ctx_mask);

    // 4. combine splits -> attention + weight_context
    combine_kernel<<<dim3(B, 8), 256>>>(att, owc);

    // 5. g_lin = wc @ W_context^T + query @ W_query^T  (2 operands x 8 k-splits)
    gemm_nt<<<dim3(D / BN, 2 * KS), 256>>>(pwc, W_context, query, W_query, plin);

    // 6. out = tanh(g_lin)
    tanh_kernel<<<64, 256>>>(out);
}